// round 5
// baseline (speedup 1.0000x reference)
#include <cuda_runtime.h>
#include <math.h>

// Problem constants
#define NXg 302
#define NYg 394
#define Bb  16
#define Dd  128
#define KK  16
#define UNITS 96
#define SPR  25                 // strips per row (16 pts each; last has 10)
#define WPBATCH (NXg * SPR)     // 7550 strips per batch
#define TPB 512
#define BPBATCH ((WPBATCH * 2 + TPB - 1) / TPB)   // 30 (2 threads per strip)

typedef unsigned long long u64;

// ---------------------------------------------------------------------------
// f32x2 packed helpers
// ---------------------------------------------------------------------------
__device__ __forceinline__ u64 pack2f(float lo, float hi) {
    u64 d; asm("mov.b64 %0, {%1, %2};" : "=l"(d) : "f"(lo), "f"(hi)); return d;
}
__device__ __forceinline__ u64 pack2i(unsigned lo, unsigned hi) {
    u64 d; asm("mov.b64 %0, {%1, %2};" : "=l"(d) : "r"(lo), "r"(hi)); return d;
}
__device__ __forceinline__ void unpack2i(u64 s, unsigned& lo, unsigned& hi) {
    asm("mov.b64 {%0, %1}, %2;" : "=r"(lo), "=r"(hi) : "l"(s));
}
__device__ __forceinline__ u64 f2fma(u64 a, u64 b, u64 c) {
    u64 d; asm("fma.rn.f32x2 %0, %1, %2, %3;" : "=l"(d) : "l"(a), "l"(b), "l"(c)); return d;
}
__device__ __forceinline__ u64 f2add(u64 a, u64 b) {
    u64 d; asm("add.rn.f32x2 %0, %1, %2;" : "=l"(d) : "l"(a), "l"(b)); return d;
}
__device__ __forceinline__ u64 f2mul(u64 a, u64 b) {
    u64 d; asm("mul.rn.f32x2 %0, %1, %2;" : "=l"(d) : "l"(a), "l"(b)); return d;
}

#define MAGICP  0x4B4000004B400000ULL
#define NMAGICP 0xCB400000CB400000ULL
#define NONEP   0xBF800000BF800000ULL
#define C0P     0x3F8000003F800000ULL
#define BITS_LO_E 0x4B3FFF88   // bits(MAGIC) - 120
#define BITS_LO_R 0x4B3FFFFA   // bits(MAGIC) - 6
#define BITS_HI_R 0x4B400006   // bits(MAGIC) + 6

struct PolyC { u64 C5, C4, C3, C2, C1, K2EP; };

__device__ __forceinline__ u64 exp2_core(u64 ap, const PolyC& P,
                                         unsigned& z0, unsigned& z1)
{
    u64 zp = f2add(ap, MAGICP);
    u64 tp = f2add(zp, NMAGICP);
    u64 fp = f2fma(tp, NONEP, ap);          // f = a - round(a), |f|<=0.5
    u64 pp = f2fma(P.C5, fp, P.C4);
    pp = f2fma(pp, fp, P.C3);
    pp = f2fma(pp, fp, P.C2);
    pp = f2fma(pp, fp, P.C1);
    pp = f2fma(pp, fp, C0P);
    unpack2i(zp, z0, z1);
    return pp;
}

// exp2 with lower clamp at 2^-120 (anchor E)
__device__ __forceinline__ u64 exp2E(u64 ap, const PolyC& P)
{
    unsigned z0, z1, p0, p1;
    u64 pp = exp2_core(ap, P, z0, z1);
    unpack2i(pp, p0, p1);
    int n0 = max((int)z0, (int)BITS_LO_E);
    int n1 = max((int)z1, (int)BITS_LO_E);
    return pack2i(p0 + ((unsigned)n0 << 23), p1 + ((unsigned)n1 << 23));
}

// exp2 with n clamped to [-6, +6] (step ratio r; only fires in dead zones)
__device__ __forceinline__ u64 exp2R(u64 ap, const PolyC& P)
{
    unsigned z0, z1, p0, p1;
    u64 pp = exp2_core(ap, P, z0, z1);
    unpack2i(pp, p0, p1);
    int n0 = min(max((int)z0, (int)BITS_LO_R), (int)BITS_HI_R);
    int n1 = min(max((int)z1, (int)BITS_LO_R), (int)BITS_HI_R);
    return pack2i(p0 + ((unsigned)n0 << 23), p1 + ((unsigned)n1 << 23));
}

// ---------------------------------------------------------------------------
// Fused kernel, 512 threads/block.
// Prologue (cheap, split-D): 384 threads compute 32-long partial dots,
// smem reduce, one warp derives per-component constants (shuffle softmax).
// Main: thread pair (even/odd lane) splits the 16 components over one
// 16-point strip; geometric recurrence along the strip; shfl-combine.
// ---------------------------------------------------------------------------
__global__ __launch_bounds__(TPB, 2) void mdn_fused_kernel(
    const float* __restrict__ inp,
    const float* __restrict__ w,
    const float* __restrict__ bias,
    float* __restrict__ out)
{
    __shared__ float s_in[Dd];
    __shared__ float s_part[4][UNITS];
    __shared__ float s_y[UNITS];
    __shared__ u64 sp[KK * 10];   // packed-dup params

    const int b = blockIdx.y;
    const int t = threadIdx.x;

    if (t < Dd) s_in[t] = inp[b * Dd + t];
    __syncthreads();

    // split-D GEMM: chunk = t/96 (0..3), unit u = t%96, 32 MACs each
    if (t < 4 * UNITS) {
        const int chunk = t / UNITS;
        const int u     = t - chunk * UNITS;
        const float* wc = w + (chunk * 32) * UNITS + u;
        const float* ic = s_in + chunk * 32;
        float acc = 0.0f;
#pragma unroll
        for (int d = 0; d < 32; ++d)
            acc = fmaf(ic[d], wc[d * UNITS], acc);
        s_part[chunk][u] = acc;
    }
    __syncthreads();

    if (t < UNITS)
        s_y[t] = bias[t] + ((s_part[0][t] + s_part[1][t]) +
                            (s_part[2][t] + s_part[3][t]));
    __syncthreads();

    if (t < KK) {
        const int k = t;
        const float mux = s_y[2 * k];
        const float muy = s_y[2 * k + 1];
        const float aa  = s_y[2 * KK + 3 * k];
        const float s22 = s_y[2 * KK + 3 * k + 1];
        const float s11 = s_y[2 * KK + 3 * k + 2];
        const float pik = s_y[5 * KK + k];

        // shuffle softmax stats across lanes 0..15
        float m = pik;
#pragma unroll
        for (int s = 1; s < KK; s <<= 1)
            m = fmaxf(m, __shfl_xor_sync(0x0000FFFFu, m, s));
        float S = expf(pik - m);
#pragma unroll
        for (int s = 1; s < KK; s <<= 1)
            S += __shfl_xor_sync(0x0000FFFFu, S, s);

        const float A1 = expf(-s11);
        const float A2 = expf(-s22);
        const float LOG2E    = 1.4426950408889634f;
        const float LOG2_2PI = 2.6514961294723187f;
        const float K2E      = -0.7213475204444817f;   // -0.5*log2(e)
        const float LC = (pik - m - s11 - s22) * LOG2E - log2f(S) - LOG2_2PI;

        const float dyv = 1.0f / (NYg - 1);
        const float Sstep = 2.0f * A2 * dyv;           // z2 step for dj=2
        const float G1 = 2.0f * K2E * Sstep;
        const float G0 = K2E * Sstep * Sstep;
        const float c  = exp2f(G1 * Sstep);            // ratio of ratios

        u64* P = &sp[k * 10];
        P[0] = pack2f(A1, A1);
        P[1] = pack2f(-mux * A1, -mux * A1);
        P[2] = pack2f(A2, A2);
        P[3] = pack2f(-muy * A2, -muy * A2);
        P[4] = pack2f(-aa * A2, -aa * A2);
        P[5] = pack2f(LC, LC);
        P[6] = pack2f(G1, G1);
        P[7] = pack2f(G0, G0);
        P[8] = pack2f(c, c);
        P[9] = 0ULL;
    }
    __syncthreads();

    // ---- main eval ----
    const int gt    = blockIdx.x * TPB + t;
    const int wi0   = gt >> 1;               // strip index (2 threads/strip)
    const int khalf = t & 1;
    const bool valid = (wi0 < WPBATCH);
    const int wi = valid ? wi0 : (WPBATCH - 1);

    const int i     = wi / SPR;
    const int strip = wi - i * SPR;
    const int j0    = strip * 16;

    const float x  = (float)i * (1.0f / (NXg - 1));
    const float y0 = (float)j0 * (1.0f / (NYg - 1));
    const float y1 = (float)(j0 + 1) * (1.0f / (NYg - 1));

    const u64 xp = pack2f(x, x);
    const u64 yp = pack2f(y0, y1);

    PolyC P;
    P.C5 = pack2f(1.3333558e-3f, 1.3333558e-3f);
    P.C4 = pack2f(9.6181291e-3f, 9.6181291e-3f);
    P.C3 = pack2f(5.5504109e-2f, 5.5504109e-2f);
    P.C2 = pack2f(2.4022651e-1f, 2.4022651e-1f);
    P.C1 = pack2f(6.9314718e-1f, 6.9314718e-1f);
    P.K2EP = pack2f(-0.7213475204444817f, -0.7213475204444817f);

    u64 acc[8];
#pragma unroll
    for (int n = 0; n < 8; ++n) acc[n] = 0ULL;

    const int kbase = khalf * (KK / 2);
#pragma unroll
    for (int kk = 0; kk < KK / 2; ++kk) {
        const int k = kbase + kk;
        const ulonglong2 q0 = *reinterpret_cast<const ulonglong2*>(&sp[k * 10 + 0]); // A1,B1
        const ulonglong2 q1 = *reinterpret_cast<const ulonglong2*>(&sp[k * 10 + 2]); // A2,B2
        const ulonglong2 q2 = *reinterpret_cast<const ulonglong2*>(&sp[k * 10 + 4]); // C2,LC
        const ulonglong2 q3 = *reinterpret_cast<const ulonglong2*>(&sp[k * 10 + 6]); // G1,G0
        const u64 cP = sp[k * 10 + 8];

        u64 z1  = f2fma(xp, q0.x, q0.y);
        u64 z1s = f2mul(z1, z1);
        u64 W   = f2fma(q2.x, z1, q1.y);
        u64 z2  = f2fma(yp, q1.x, W);
        u64 m   = f2fma(z2, z2, z1s);
        u64 a0  = f2fma(m, P.K2EP, q2.y);
        u64 E   = exp2E(a0, P);
        u64 dq  = f2fma(z2, q3.x, q3.y);
        u64 r   = exp2R(dq, P);

        acc[0] = f2add(acc[0], E);
#pragma unroll
        for (int n = 1; n < 8; ++n) {
            E = f2mul(E, r);
            if (n < 7) r = f2mul(r, cP);
            acc[n] = f2add(acc[n], E);
        }
    }

    // combine the two k-halves (lanes 2s / 2s+1)
#pragma unroll
    for (int n = 0; n < 8; ++n) {
        u64 o = __shfl_xor_sync(0xFFFFFFFFu, acc[n], 1);
        acc[n] = f2add(acc[n], o);
    }

    if (valid) {
        u64* o64 = reinterpret_cast<u64*>(out);
        const size_t base = (size_t)(b * NXg + i) * (NYg / 2) + strip * 8;
        const int npairs = (strip < SPR - 1) ? 8 : 5;
        if (khalf == 0) {
#pragma unroll
            for (int n = 0; n < 4; ++n) o64[base + n] = acc[n];
        } else {
#pragma unroll
            for (int n = 4; n < 8; ++n)
                if (n < npairs) o64[base + n] = acc[n];
        }
    }
}

// ---------------------------------------------------------------------------
extern "C" void kernel_launch(void* const* d_in, const int* in_sizes, int n_in,
                              void* d_out, int out_size)
{
    const float* inp  = (const float*)d_in[0];   // [16,128]
    const float* w    = (const float*)d_in[1];   // [128,96]
    const float* bias = (const float*)d_in[2];   // [96]
    float* out = (float*)d_out;                  // [16,302,394,1]

    dim3 grid(BPBATCH, Bb);
    mdn_fused_kernel<<<grid, TPB>>>(inp, w, bias, out);
}

// round 6
// speedup vs baseline: 1.1245x; 1.1245x over previous
#include <cuda_runtime.h>
#include <math.h>

// Problem constants
#define NXg 302
#define NYg 394
#define Bb  16
#define Dd  128
#define KK  16
#define UNITS 96
#define SPR  25                 // strips per row (16 pts each; last has 10)
#define WPBATCH (NXg * SPR)     // 7550 strips per batch
#define TPB 256
#define BPBATCH ((WPBATCH * 2 + TPB - 1) / TPB)   // 60 (2 threads per strip)

typedef unsigned long long u64;

// ---------------------------------------------------------------------------
// f32x2 packed helpers
// ---------------------------------------------------------------------------
__device__ __forceinline__ u64 pack2f(float lo, float hi) {
    u64 d; asm("mov.b64 %0, {%1, %2};" : "=l"(d) : "f"(lo), "f"(hi)); return d;
}
__device__ __forceinline__ void unpack2f(u64 s, float& lo, float& hi) {
    asm("mov.b64 {%0, %1}, %2;" : "=f"(lo), "=f"(hi) : "l"(s));
}
__device__ __forceinline__ u64 f2fma(u64 a, u64 b, u64 c) {
    u64 d; asm("fma.rn.f32x2 %0, %1, %2, %3;" : "=l"(d) : "l"(a), "l"(b), "l"(c)); return d;
}
__device__ __forceinline__ u64 f2add(u64 a, u64 b) {
    u64 d; asm("add.rn.f32x2 %0, %1, %2;" : "=l"(d) : "l"(a), "l"(b)); return d;
}
__device__ __forceinline__ u64 f2mul(u64 a, u64 b) {
    u64 d; asm("mul.rn.f32x2 %0, %1, %2;" : "=l"(d) : "l"(a), "l"(b)); return d;
}
__device__ __forceinline__ float ex2a(float x) {
    float y; asm("ex2.approx.f32 %0, %1;" : "=f"(y) : "f"(x)); return y;
}

// packed exp2 via MUFU, arg clamped below at -120 (anchor E)
__device__ __forceinline__ u64 exp2E(u64 ap)
{
    float a0, a1; unpack2f(ap, a0, a1);
    float e0 = ex2a(fmaxf(a0, -120.0f));
    float e1 = ex2a(fmaxf(a1, -120.0f));
    return pack2f(e0, e1);
}

// packed exp2 via MUFU, arg clamped to [-6, 6] (step ratio; fires only in
// dead zones where E is already ~2^-120)
__device__ __forceinline__ u64 exp2R(u64 ap)
{
    float a0, a1; unpack2f(ap, a0, a1);
    float e0 = ex2a(fminf(fmaxf(a0, -6.0f), 6.0f));
    float e1 = ex2a(fminf(fmaxf(a1, -6.0f), 6.0f));
    return pack2f(e0, e1);
}

// ---------------------------------------------------------------------------
// Fused kernel, 256 threads/block.
// Prologue: split-D GEMM (192 threads x 64 MACs) + shuffle softmax + params.
// Main: thread pair (even/odd lane) splits the 16 components over one
// 16-point strip; MUFU anchor + geometric recurrence; shfl-combine.
// ---------------------------------------------------------------------------
__global__ __launch_bounds__(TPB) void mdn_fused_kernel(
    const float* __restrict__ inp,
    const float* __restrict__ w,
    const float* __restrict__ bias,
    float* __restrict__ out)
{
    __shared__ float s_in[Dd];
    __shared__ float s_part[2][UNITS];
    __shared__ float s_y[UNITS];
    __shared__ u64 sp[KK * 10];   // packed-dup params

    const int b = blockIdx.y;
    const int t = threadIdx.x;

    if (t < Dd) s_in[t] = inp[b * Dd + t];
    __syncthreads();

    // split-D GEMM: chunk = t/96 (0..1), unit u = t%96, 64 MACs each
    if (t < 2 * UNITS) {
        const int chunk = t / UNITS;
        const int u     = t - chunk * UNITS;
        const float* wc = w + (chunk * 64) * UNITS + u;
        const float* ic = s_in + chunk * 64;
        float acc = 0.0f;
#pragma unroll
        for (int d = 0; d < 64; ++d)
            acc = fmaf(ic[d], wc[d * UNITS], acc);
        s_part[chunk][u] = acc;
    }
    __syncthreads();

    if (t < UNITS)
        s_y[t] = bias[t] + (s_part[0][t] + s_part[1][t]);
    __syncthreads();

    if (t < KK) {
        const int k = t;
        const float mux = s_y[2 * k];
        const float muy = s_y[2 * k + 1];
        const float aa  = s_y[2 * KK + 3 * k];
        const float s22 = s_y[2 * KK + 3 * k + 1];
        const float s11 = s_y[2 * KK + 3 * k + 2];
        const float pik = s_y[5 * KK + k];

        // shuffle softmax stats across lanes 0..15
        float m = pik;
#pragma unroll
        for (int s = 1; s < KK; s <<= 1)
            m = fmaxf(m, __shfl_xor_sync(0x0000FFFFu, m, s));
        float S = expf(pik - m);
#pragma unroll
        for (int s = 1; s < KK; s <<= 1)
            S += __shfl_xor_sync(0x0000FFFFu, S, s);

        const float A1 = expf(-s11);
        const float A2 = expf(-s22);
        const float LOG2E    = 1.4426950408889634f;
        const float LOG2_2PI = 2.6514961294723187f;
        const float K2E      = -0.7213475204444817f;   // -0.5*log2(e)
        const float LC = (pik - m - s11 - s22) * LOG2E - log2f(S) - LOG2_2PI;

        const float dyv = 1.0f / (NYg - 1);
        const float Sstep = 2.0f * A2 * dyv;           // z2 step for dj=2
        const float G1 = 2.0f * K2E * Sstep;
        const float G0 = K2E * Sstep * Sstep;
        const float c  = exp2f(G1 * Sstep);            // ratio of ratios

        u64* P = &sp[k * 10];
        P[0] = pack2f(A1, A1);
        P[1] = pack2f(-mux * A1, -mux * A1);
        P[2] = pack2f(A2, A2);
        P[3] = pack2f(-muy * A2, -muy * A2);
        P[4] = pack2f(-aa * A2, -aa * A2);
        P[5] = pack2f(LC, LC);
        P[6] = pack2f(G1, G1);
        P[7] = pack2f(G0, G0);
        P[8] = pack2f(c, c);
        P[9] = 0ULL;
    }
    __syncthreads();

    // ---- main eval ----
    const int gt    = blockIdx.x * TPB + t;
    const int wi0   = gt >> 1;               // strip index (2 threads/strip)
    const int khalf = t & 1;
    const bool valid = (wi0 < WPBATCH);
    const int wi = valid ? wi0 : (WPBATCH - 1);

    const int i     = wi / SPR;
    const int strip = wi - i * SPR;
    const int j0    = strip * 16;

    const float x  = (float)i * (1.0f / (NXg - 1));
    const float y0 = (float)j0 * (1.0f / (NYg - 1));
    const float y1 = (float)(j0 + 1) * (1.0f / (NYg - 1));

    const u64 xp = pack2f(x, x);
    const u64 yp = pack2f(y0, y1);
    const u64 K2EP = 0xBF38AA3BBF38AA3BULL;  // {-0.72134752f, -0.72134752f}

    u64 acc[8];
#pragma unroll
    for (int n = 0; n < 8; ++n) acc[n] = 0ULL;

    const int kbase = khalf * (KK / 2);
#pragma unroll
    for (int kk = 0; kk < KK / 2; ++kk) {
        const int k = kbase + kk;
        const ulonglong2 q0 = *reinterpret_cast<const ulonglong2*>(&sp[k * 10 + 0]); // A1,B1
        const ulonglong2 q1 = *reinterpret_cast<const ulonglong2*>(&sp[k * 10 + 2]); // A2,B2
        const ulonglong2 q2 = *reinterpret_cast<const ulonglong2*>(&sp[k * 10 + 4]); // C2,LC
        const ulonglong2 q3 = *reinterpret_cast<const ulonglong2*>(&sp[k * 10 + 6]); // G1,G0
        const u64 cP = sp[k * 10 + 8];

        u64 z1  = f2fma(xp, q0.x, q0.y);
        u64 z1s = f2mul(z1, z1);
        u64 W   = f2fma(q2.x, z1, q1.y);
        u64 z2  = f2fma(yp, q1.x, W);
        u64 m   = f2fma(z2, z2, z1s);
        u64 a0  = f2fma(m, K2EP, q2.y);
        u64 E   = exp2E(a0);
        u64 dq  = f2fma(z2, q3.x, q3.y);
        u64 r   = exp2R(dq);

        acc[0] = f2add(acc[0], E);
#pragma unroll
        for (int n = 1; n < 8; ++n) {
            E = f2mul(E, r);
            if (n < 7) r = f2mul(r, cP);
            acc[n] = f2add(acc[n], E);
        }
    }

    // combine the two k-halves (lanes 2s / 2s+1)
#pragma unroll
    for (int n = 0; n < 8; ++n) {
        u64 o = __shfl_xor_sync(0xFFFFFFFFu, acc[n], 1);
        acc[n] = f2add(acc[n], o);
    }

    if (valid) {
        u64* o64 = reinterpret_cast<u64*>(out);
        const size_t base = (size_t)(b * NXg + i) * (NYg / 2) + strip * 8;
        const int npairs = (strip < SPR - 1) ? 8 : 5;
        if (khalf == 0) {
#pragma unroll
            for (int n = 0; n < 4; ++n) o64[base + n] = acc[n];
        } else {
#pragma unroll
            for (int n = 4; n < 8; ++n)
                if (n < npairs) o64[base + n] = acc[n];
        }
    }
}

// ---------------------------------------------------------------------------
extern "C" void kernel_launch(void* const* d_in, const int* in_sizes, int n_in,
                              void* d_out, int out_size)
{
    const float* inp  = (const float*)d_in[0];   // [16,128]
    const float* w    = (const float*)d_in[1];   // [128,96]
    const float* bias = (const float*)d_in[2];   // [96]
    float* out = (float*)d_out;                  // [16,302,394,1]

    dim3 grid(BPBATCH, Bb);
    mdn_fused_kernel<<<grid, TPB>>>(inp, w, bias, out);
}